// round 7
// baseline (speedup 1.0000x reference)
#include <cuda_runtime.h>
#include <math.h>

#define NB 16384
#define NM 50
#define ND 64

#define FULLM 0xffffffffu

__global__ __launch_bounds__(64, 16)
void agree_kernel(
    const int* __restrict__ group_inputs,
    const int* __restrict__ item_inputs,
    const int* __restrict__ member_ids,
    const int* __restrict__ member_lengths,
    const float* __restrict__ user_table,
    const float* __restrict__ item_table,
    const float* __restrict__ group_table,
    const float* __restrict__ att_w1,
    const float* __restrict__ att_b1,
    const float* __restrict__ att_w2,
    const float* __restrict__ att_b2,
    const float* __restrict__ pred_w1,
    const float* __restrict__ pred_b1,
    const float* __restrict__ pred_w2,
    const float* __restrict__ pred_b2,
    float* __restrict__ out)
{
    // per-warp member pair staging, double buffered. One member = 72 words:
    // d[0..31] at 0..31, d[32..63] at 36..67 (pad kills bank aliasing).
    __shared__ __align__(16) float s_me[2][2][2][72];
    __shared__ __align__(16) float s_new[3 * ND];   // [elem | g | item_e]
    __shared__ __align__(16) float s_part[2][ND];   // per-warp pooled-g partials
    __shared__ float s_dsum[2];

    const int tid  = threadIdx.x;
    const int w    = tid >> 5;    // warp in row (0/1): owns pairs w, w+2, ...
    const int lane = tid & 31;
    const int b    = blockIdx.x;

    const int c0 = lane & 15;   // att hidden unit / float4-chunk this lane owns
    const int h  = lane >> 4;   // d-half AND "own member" of this lane

    float* s_item = &s_new[2 * ND];

    // ---- item embedding into smem (warp 0), ids into regs (both warps) ----
    if (w == 0) {
        const float* itrow = item_table + (size_t)item_inputs[b] * ND;
        s_item[lane]      = itrow[lane];
        s_item[lane + 32] = itrow[lane + 32];
    }
    const int idsA = member_ids[b * NM + lane];
    const int idsB = (lane < NM - 32) ? member_ids[b * NM + 32 + lane] : 0;

    // ---- W1a slice: column c0, d-range [h*32, h*32+32)  (32 regs) ----
    float wc[32];
    #pragma unroll
    for (int k = 0; k < 32; k++) wc[k] = att_w1[(h * 32 + k) * 16 + c0];

    __syncthreads();   // s_item visible to both warps

    // ---- cconst[c0] = att_b1 + item_e @ W1b, split per d-half + combine ----
    float cconst;
    {
        float cc = 0.f;
        const float4* si4 = (const float4*)(s_item + h * 32);
        #pragma unroll
        for (int dd = 0; dd < 8; dd++) {
            float4 v = si4[dd];
            int db = (ND + h * 32 + 4 * dd) * 16 + c0;
            cc = fmaf(v.x, att_w1[db],      cc);
            cc = fmaf(v.y, att_w1[db + 16], cc);
            cc = fmaf(v.z, att_w1[db + 32], cc);
            cc = fmaf(v.w, att_w1[db + 48], cc);
        }
        cconst = cc + __shfl_xor_sync(FULLM, cc, 16) + att_b1[c0];
    }

    const float w2c = att_w2[c0];
    const float b2  = att_b2[0];
    const int  len  = member_lengths[b];     // member m valid iff m <= len
    const int  npairs = (len >> 1) + 1;

    // plain-exp softmax partials (scores O(0.3) by construction — no max shift)
    float dsum = 0.f;
    float4 gq = make_float4(0.f, 0.f, 0.f, 0.f);

    // ---- preload this warp's first pair (pw = w) ----
    float4 r;
    if (w < npairs) {
        int m = 2 * w + h;
        int mid = __shfl_sync(FULLM, (m < 32) ? idsA : idsB, m & 31);
        r = ((const float4*)(user_table + (size_t)mid * ND))[c0];
    }

    float* const meb = &s_me[w][0][0][0];            // buf stride 144 words
    const int stoff = 4 * c0 + ((c0 >= 8) ? 4 : 0);  // padded store offset

    #pragma unroll 1
    for (int pw = w; pw < npairs; pw += 2) {
        float* mb = meb + ((pw >> 1) & 1) * 144;

        // stage pair pw; keep own-member chunk in regs for g-accumulation
        *(float4*)(mb + h * 72 + stoff) = r;
        float4 cur = r;
        __syncwarp();

        // prefetch pair pw+2 (latency covered by this pair's compute)
        if (pw + 2 < npairs) {
            int m = 2 * (pw + 2) + h;
            int mid = __shfl_sync(FULLM, (m < 32) ? idsA : idsB, m & 31);
            r = ((const float4*)(user_table + (size_t)mid * ND))[c0];
        }

        // partial dots over this lane's 32-d slice, both members
        const float4* me0 = (const float4*)(mb + h * 36);
        const float4* me1 = (const float4*)(mb + 72 + h * 36);
        float p0a = 0.f, p0b = 0.f, p1a = 0.f, p1b = 0.f;
        #pragma unroll
        for (int i = 0; i < 8; i += 2) {
            float4 a = me0[i];
            p0a = fmaf(a.x, wc[4 * i + 0], p0a);
            p0a = fmaf(a.y, wc[4 * i + 1], p0a);
            p0a = fmaf(a.z, wc[4 * i + 2], p0a);
            p0a = fmaf(a.w, wc[4 * i + 3], p0a);
            float4 a2 = me0[i + 1];
            p0b = fmaf(a2.x, wc[4 * i + 4], p0b);
            p0b = fmaf(a2.y, wc[4 * i + 5], p0b);
            p0b = fmaf(a2.z, wc[4 * i + 6], p0b);
            p0b = fmaf(a2.w, wc[4 * i + 7], p0b);
            float4 e = me1[i];
            p1a = fmaf(e.x, wc[4 * i + 0], p1a);
            p1a = fmaf(e.y, wc[4 * i + 1], p1a);
            p1a = fmaf(e.z, wc[4 * i + 2], p1a);
            p1a = fmaf(e.w, wc[4 * i + 3], p1a);
            float4 e2 = me1[i + 1];
            p1b = fmaf(e2.x, wc[4 * i + 4], p1b);
            p1b = fmaf(e2.y, wc[4 * i + 5], p1b);
            p1b = fmaf(e2.z, wc[4 * i + 6], p1b);
            p1b = fmaf(e2.w, wc[4 * i + 7], p1b);
        }
        float p0 = p0a + p0b;   // member0 of pair, this lane's d-half
        float p1 = p1a + p1b;   // member1 of pair, this lane's d-half

        // own-member assembly: lane (c0,h) gets full column-c0 dot of member h
        float u = h ? p1 : p0;
        float v = h ? p0 : p1;
        float A = u + __shfl_xor_sync(FULLM, v, 16);
        float t = fmaxf(A + cconst, 0.f) * w2c;

        // butterfly over 16 columns within each half (halves disjoint)
        t += __shfl_xor_sync(FULLM, t, 1);
        t += __shfl_xor_sync(FULLM, t, 2);
        t += __shfl_xor_sync(FULLM, t, 4);
        t += __shfl_xor_sync(FULLM, t, 8);

        // own-member weight; h=0 always valid in-loop
        float e = (2 * pw + h <= len) ? __expf(t + b2) : 0.f;
        dsum += e;
        gq.x = fmaf(e, cur.x, gq.x);
        gq.y = fmaf(e, cur.y, gq.y);
        gq.z = fmaf(e, cur.z, gq.z);
        gq.w = fmaf(e, cur.w, gq.w);
    }

    // ---- per-warp cross-half combine, publish partials ----
    gq.x += __shfl_xor_sync(FULLM, gq.x, 16);
    gq.y += __shfl_xor_sync(FULLM, gq.y, 16);
    gq.z += __shfl_xor_sync(FULLM, gq.z, 16);
    gq.w += __shfl_xor_sync(FULLM, gq.w, 16);
    dsum += __shfl_xor_sync(FULLM, dsum, 16);
    if (lane < 16) ((float4*)s_part[w])[c0] = gq;
    if (lane == 0) s_dsum[w] = dsum;
    __syncthreads();

    if (w == 0) {
        // ---- merge partials; g = pooled members + group embedding ----
        float4 gA = ((const float4*)s_part[0])[c0];
        float4 gB = ((const float4*)s_part[1])[c0];
        const float inv = 1.0f / (s_dsum[0] + s_dsum[1]);

        const size_t gid = (size_t)group_inputs[b];
        float4 grp = ((const float4*)(group_table + gid * ND))[c0];
        float4 it4 = ((const float4*)s_item)[c0];

        float4 gg, el;
        gg.x = fmaf(gA.x + gB.x, inv, grp.x);  el.x = gg.x * it4.x;
        gg.y = fmaf(gA.y + gB.y, inv, grp.y);  el.y = gg.y * it4.y;
        gg.z = fmaf(gA.z + gB.z, inv, grp.z);  el.z = gg.z * it4.z;
        gg.w = fmaf(gA.w + gB.w, inv, grp.w);  el.w = gg.w * it4.w;

        // both halves hold identical values; duplicate stores are benign
        ((float4*)&s_new[0])[c0]  = el;   // elem
        ((float4*)&s_new[ND])[c0] = gg;   // g
        __syncwarp();

        // ---- predict MLP: new_e[192] -> 8 -> 1 -> sigmoid ----
        const int j = lane & 7;        // hidden unit
        const int q = lane >> 3;       // k-quarter (48 elems each)
        float ph = 0.f;
        #pragma unroll 12
        for (int i = 0; i < 48; i++) {
            int k = q * 48 + i;
            ph = fmaf(s_new[k], pred_w1[k * 8 + j], ph);
        }
        ph += __shfl_xor_sync(FULLM, ph, 8);
        ph += __shfl_xor_sync(FULLM, ph, 16);

        float hj = fmaxf(ph + pred_b1[j], 0.f);
        float t2 = hj * pred_w2[j];
        t2 += __shfl_xor_sync(FULLM, t2, 1);
        t2 += __shfl_xor_sync(FULLM, t2, 2);
        t2 += __shfl_xor_sync(FULLM, t2, 4);

        if (lane == 0) {
            float z = t2 + pred_b2[0];
            out[b] = 1.0f / (1.0f + __expf(-z));
        }
    }
}

extern "C" void kernel_launch(void* const* d_in, const int* in_sizes, int n_in,
                              void* d_out, int out_size) {
    (void)in_sizes; (void)n_in; (void)out_size;
    agree_kernel<<<NB, 64>>>(
        (const int*)d_in[0],   // group_inputs
        (const int*)d_in[1],   // item_inputs
        (const int*)d_in[2],   // member_ids
        (const int*)d_in[3],   // member_lengths
        (const float*)d_in[4], // user_table
        (const float*)d_in[5], // item_table
        (const float*)d_in[6], // group_table
        (const float*)d_in[7], // att_w1
        (const float*)d_in[8], // att_b1
        (const float*)d_in[9], // att_w2
        (const float*)d_in[10],// att_b2
        (const float*)d_in[11],// pred_w1
        (const float*)d_in[12],// pred_b1
        (const float*)d_in[13],// pred_w2
        (const float*)d_in[14],// pred_b2
        (float*)d_out);
}